// round 6
// baseline (speedup 1.0000x reference)
#include <cuda_runtime.h>
#include <cuda_bf16.h>
#include <cstdint>

// Problem constants
#define NW   8192
#define NTOK 64
#define CDIM 180
#define HEADS 6
#define HD   30
#define NW_PER_IMG 1024

// Scratch (allocation-guard-safe: __device__ globals)
__device__ float g_qkv[(long long)NW * NTOK * (3 * CDIM)];   // [nW*N, 540]
__device__ float g_att[(long long)NW * NTOK * CDIM];         // [nW*N, 180]

// ===========================================================================
// f32x2 paired-fp32 helpers (Blackwell)
// ===========================================================================
__device__ __forceinline__ unsigned long long fma2(unsigned long long a,
                                                   unsigned long long b,
                                                   unsigned long long c) {
    unsigned long long d;
    asm("fma.rn.f32x2 %0, %1, %2, %3;" : "=l"(d) : "l"(a), "l"(b), "l"(c));
    return d;
}
__device__ __forceinline__ unsigned long long add2(unsigned long long a,
                                                   unsigned long long b) {
    unsigned long long d;
    asm("add.rn.f32x2 %0, %1, %2;" : "=l"(d) : "l"(a), "l"(b));
    return d;
}
__device__ __forceinline__ unsigned long long mul2(unsigned long long a,
                                                   unsigned long long b) {
    unsigned long long d;
    asm("mul.rn.f32x2 %0, %1, %2;" : "=l"(d) : "l"(a), "l"(b));
    return d;
}
__device__ __forceinline__ unsigned long long pack2(float lo, float hi) {
    unsigned long long r;
    asm("mov.b64 %0, {%1, %2};" : "=l"(r) : "f"(lo), "f"(hi));
    return r;
}
__device__ __forceinline__ void unpack2(float& lo, float& hi, unsigned long long v) {
    asm("mov.b64 {%0, %1}, %2;" : "=f"(lo), "=f"(hi) : "l"(v));
}

// ===========================================================================
// tf32 helpers
// ===========================================================================
__device__ __forceinline__ float f2tf32(float x) {
    unsigned u;
    asm("cvt.rna.tf32.f32 %0, %1;" : "=r"(u) : "f"(x));
    return __uint_as_float(u);
}

__device__ __forceinline__ void mma_tf32(float d[4], const float a[4], const float b[2]) {
    const unsigned* A = reinterpret_cast<const unsigned*>(a);
    const unsigned* B = reinterpret_cast<const unsigned*>(b);
    asm volatile(
        "mma.sync.aligned.m16n8k8.row.col.f32.tf32.tf32.f32 "
        "{%0,%1,%2,%3},{%4,%5,%6,%7},{%8,%9},{%0,%1,%2,%3};\n"
        : "+f"(d[0]), "+f"(d[1]), "+f"(d[2]), "+f"(d[3])
        : "r"(A[0]), "r"(A[1]), "r"(A[2]), "r"(A[3]), "r"(B[0]), "r"(B[1]));
}

__device__ __forceinline__ void cp_async16(unsigned dst, const void* src, int src_bytes) {
    asm volatile("cp.async.cg.shared.global [%0], [%1], 16, %2;\n"
                 :: "r"(dst), "l"(src), "r"(src_bytes));
}
__device__ __forceinline__ void cp_commit() {
    asm volatile("cp.async.commit_group;\n" ::: "memory");
}
__device__ __forceinline__ void cp_wait1() {
    asm volatile("cp.async.wait_group 1;\n" ::: "memory");
}

// ===========================================================================
// GEMM (TN): C[M,N] = A[M,180] @ B[N,180]^T + bias[N]
// BM=128, BN=128, BK=32, 3-stage cp.async pipeline, 256 threads, tf32 mma.
// Fragments rounded with cvt.rna.tf32 post-LDS for accuracy.
// ===========================================================================
#define GROWS 36                    // smem row stride (words)
#define GSTAGE_WORDS (256 * GROWS)
#define GNITER 6

__global__ __launch_bounds__(256, 2) void mma_gemm_tn(
    const float* __restrict__ A, const float* __restrict__ B,
    const float* __restrict__ bias, float* __restrict__ C, int N)
{
    extern __shared__ float sm[];
    const int tid = threadIdx.x;
    const int row0 = blockIdx.y * 128;
    const int col0 = blockIdx.x * 128;

    const unsigned sbase = (unsigned)__cvta_generic_to_shared(sm);

    auto stage_load = [&](int s, int ki) {
        const int k0 = ki * 32;
        const unsigned stW = sbase + (unsigned)(s * GSTAGE_WORDS) * 4u;
#pragma unroll
        for (int j = 0; j < 8; j++) {
            int idx = tid + j * 256;            // 0..2047
            int r  = (idx & 1023) >> 3;         // row 0..127
            int c4 = idx & 7;
            int gk = k0 + c4 * 4;
            int gkc = gk <= 176 ? gk : 176;
            if (idx < 1024) {
                int bytes = (gk <= 176) ? 16 : 0;
                const float* src = A + (size_t)(row0 + r) * CDIM + gkc;
                cp_async16(stW + (unsigned)(r * GROWS + c4 * 4) * 4u, src, bytes);
            } else {
                int nn = col0 + r;
                int ok = (nn < N) && (gk <= 176);
                const float* src = B + (size_t)(ok ? nn : 0) * CDIM + gkc;
                cp_async16(stW + (unsigned)(128 * GROWS + r * GROWS + c4 * 4) * 4u,
                           src, ok ? 16 : 0);
            }
        }
    };

    stage_load(0, 0); cp_commit();
    stage_load(1, 1); cp_commit();
    cp_wait1();
    __syncthreads();

    const int warp = tid >> 5;
    const int lane = tid & 31;
    const int wm = warp & 1;          // 0..1 -> 64 rows
    const int wn = warp >> 1;         // 0..3 -> 32 cols
    const int g = lane >> 2;
    const int t = lane & 3;

    float acc[4][4][4];
#pragma unroll
    for (int mt = 0; mt < 4; mt++)
#pragma unroll
        for (int nt = 0; nt < 4; nt++)
#pragma unroll
            for (int e = 0; e < 4; e++) acc[mt][nt][e] = 0.f;

#pragma unroll 1
    for (int ks = 0; ks < GNITER; ks++) {
        if (ks + 2 < GNITER) stage_load((ks + 2) % 3, ks + 2);
        cp_commit();

        const float* sA = sm + (ks % 3) * GSTAGE_WORDS;
        const float* sB = sA + 128 * GROWS;

#pragma unroll
        for (int step = 0; step < 4; step++) {
            const int kb = step * 8;
            float a[4][4], b[4][2];
#pragma unroll
            for (int mt = 0; mt < 4; mt++) {
                int base = (wm * 64 + mt * 16 + g) * GROWS + kb + t;
                a[mt][0] = f2tf32(sA[base]);
                a[mt][1] = f2tf32(sA[base + 8 * GROWS]);
                a[mt][2] = f2tf32(sA[base + 4]);
                a[mt][3] = f2tf32(sA[base + 8 * GROWS + 4]);
            }
#pragma unroll
            for (int nt = 0; nt < 4; nt++) {
                int bb = (wn * 32 + nt * 8 + g) * GROWS + kb + t;
                b[nt][0] = f2tf32(sB[bb]);
                b[nt][1] = f2tf32(sB[bb + 4]);
            }
#pragma unroll
            for (int mt = 0; mt < 4; mt++)
#pragma unroll
                for (int nt = 0; nt < 4; nt++)
                    mma_tf32(acc[mt][nt], a[mt], b[nt]);
        }
        cp_wait1();
        __syncthreads();
    }

    // Epilogue
#pragma unroll
    for (int mt = 0; mt < 4; mt++) {
#pragma unroll
        for (int nt = 0; nt < 4; nt++) {
            int row = row0 + wm * 64 + mt * 16 + g;
            int col = col0 + wn * 32 + nt * 8 + 2 * t;
            if (col < N) {
                float b0 = bias[col], b1 = bias[col + 1];
                float2 v0 = make_float2(acc[mt][nt][0] + b0, acc[mt][nt][1] + b1);
                float2 v1 = make_float2(acc[mt][nt][2] + b0, acc[mt][nt][3] + b1);
                *(float2*)(C + (size_t)row * N + col) = v0;
                *(float2*)(C + (size_t)(row + 8) * N + col) = v1;
            }
        }
    }
}

// ===========================================================================
// Attention: one block per (window, head-pair). 256 threads:
//   half = tid>>7   -> key-range split (m in [half*32, half*32+32))
//   hl   = (tid>>6)&1 -> head within pair
//   n    = tid&63   -> query row
// Partial (o, sum) from half 1 combined with half 0 through smem.
// smem layout (floats):
//   [0)      sQ [2][64][36]   (4608)  -- reused for partials + output staging
//   [4608)   sK [2][64][36]   (4608)
//   [9216)   sV [2][64][36]   (4608)
//   [13824)  sM [64][65]      (4160)
//   [17984)  sR [2][225]      (450)
//   [18434)  sSum [128]
// total 18562 floats = 74248 B
// ===========================================================================
#define ATT_SMEM_FLOATS 18562

__global__ __launch_bounds__(256) void attn_kernel(
    const float* __restrict__ qkv, const float* __restrict__ mask,
    const float* __restrict__ rpb, float* __restrict__ out)
{
    extern __shared__ float sm[];
    float* sM = sm + 13824;
    float* sR = sm + 17984;
    float* sSum = sm + 18434;

    const int w = blockIdx.x;
    const int h0 = blockIdx.y * 2;
    const int tid = threadIdx.x;

    // ---- stage q/k/v slices (coalesced) ----
    for (int i = tid; i < 2880; i += 256) {
        int arr = i / 960;                   // 0=q 1=k 2=v
        int rem = i - arr * 960;
        int r = rem / 15, c4 = rem - r * 15;
        float4 v = *(const float4*)(qkv + (size_t)(w * NTOK + r) * (3 * CDIM)
                                    + arr * CDIM + h0 * HD + c4 * 4);
        float* dst = sm + arr * 4608;
        const float* vf = (const float*)&v;
#pragma unroll
        for (int j = 0; j < 4; j++) {
            int d = c4 * 4 + j;
            int hh = d >= 30;
            dst[hh * 2304 + r * GROWS + (d - 30 * hh)] = vf[j];
        }
    }
    // zero pad d=30,31 for k and v (q pad unused)
    for (int i = tid; i < 768; i += 256) {
        int arr = i / 256;
        int rem = i - arr * 256;
        int hh = rem >> 7;
        int r = (rem & 127) >> 1;
        sm[arr * 4608 + hh * 2304 + r * GROWS + 30 + (rem & 1)] = 0.f;
    }
    // stage mask tile
    {
        const int wi = w & (NW_PER_IMG - 1);
        const float4* mbase = (const float4*)(mask + (size_t)wi * NTOK * NTOK);
        for (int i = tid; i < 1024; i += 256) {
            float4 v = mbase[i];
            int r = i >> 4, c = (i & 15) * 4;
            sM[r * 65 + c + 0] = v.x; sM[r * 65 + c + 1] = v.y;
            sM[r * 65 + c + 2] = v.z; sM[r * 65 + c + 3] = v.w;
        }
    }
    // stage rpb rows for both heads
    for (int i = tid; i < 450; i += 256) {
        int hh = i / 225, idx = i - hh * 225;
        sR[hh * 225 + idx] = rpb[idx * HEADS + h0 + hh];
    }
    __syncthreads();

    const int half = tid >> 7;
    const int hl = (tid >> 6) & 1;
    const int n = tid & 63;

    // q into packed regs, pre-scaled
    const float scale = rsqrtf((float)HD);
    const unsigned long long scale2 = pack2(scale, scale);
    unsigned long long q2[16];
    {
        const float* qrow = sm + hl * 2304 + n * GROWS;
#pragma unroll
        for (int dq = 0; dq < 8; dq++) {
            ulonglong2 tq = *(const ulonglong2*)(qrow + dq * 4);
            q2[2 * dq + 0] = mul2(tq.x, scale2);
            q2[2 * dq + 1] = mul2(tq.y, scale2);
        }
    }
    __syncthreads();   // all q2 loaded before half 1 overwrites sQ with partials

    const float* krow0 = sm + 4608 + hl * 2304;
    const float* vrow0 = sm + 9216 + hl * 2304;
    const float* rph = sR + hl * 225;
    const float* mrow = sM + n * 65;
    const int i1 = n >> 3, j1 = n & 7;

    unsigned long long o2[16];
#pragma unroll
    for (int j = 0; j < 16; j++) o2[j] = 0ull;
    float osum = 0.f;

    const int m0 = half * 32;
#pragma unroll 2
    for (int mm = 0; mm < 32; mm++) {
        const int m = m0 + mm;
        const float* kr = krow0 + m * GROWS;
        unsigned long long a0 = 0ull, a1 = 0ull, a2 = 0ull, a3 = 0ull;
#pragma unroll
        for (int dq = 0; dq < 4; dq++) {
            ulonglong2 k0 = *(const ulonglong2*)(kr + dq * 8);
            ulonglong2 k1 = *(const ulonglong2*)(kr + dq * 8 + 4);
            a0 = fma2(q2[4 * dq + 0], k0.x, a0);
            a1 = fma2(q2[4 * dq + 1], k0.y, a1);
            a2 = fma2(q2[4 * dq + 2], k1.x, a2);
            a3 = fma2(q2[4 * dq + 3], k1.y, a3);
        }
        unsigned long long asum = add2(add2(a0, a1), add2(a2, a3));
        float slo, shi;
        unpack2(slo, shi, asum);
        int i2 = m >> 3, j2 = m & 7;
        int idx = (i1 - i2 + 7) * 15 + (j1 - j2 + 7);
        float s = slo + shi + rph[idx] + mrow[m];

        float p = __expf(s);
        osum += p;
        unsigned long long p2 = pack2(p, p);

        const float* vr = vrow0 + m * GROWS;
#pragma unroll
        for (int dq = 0; dq < 4; dq++) {
            ulonglong2 v0 = *(const ulonglong2*)(vr + dq * 8);
            ulonglong2 v1 = *(const ulonglong2*)(vr + dq * 8 + 4);
            o2[4 * dq + 0] = fma2(p2, v0.x, o2[4 * dq + 0]);
            o2[4 * dq + 1] = fma2(p2, v0.y, o2[4 * dq + 1]);
            o2[4 * dq + 2] = fma2(p2, v1.x, o2[4 * dq + 2]);
            o2[4 * dq + 3] = fma2(p2, v1.y, o2[4 * dq + 3]);
        }
    }

    // half 1 publishes partials into the sQ area
    if (half == 1) {
        float* od = sm + hl * 2304 + n * GROWS;
#pragma unroll
        for (int j = 0; j < 15; j++)
            *(unsigned long long*)(od + 2 * j) = o2[j];
        sSum[hl * 64 + n] = osum;
    }
    __syncthreads();

    // half 0 combines, normalizes, writes result back into sQ area
    if (half == 0) {
        float* od = sm + hl * 2304 + n * GROWS;
        const float inv = 1.f / (osum + sSum[hl * 64 + n]);
        const unsigned long long inv2 = pack2(inv, inv);
#pragma unroll
        for (int j = 0; j < 15; j++) {
            unsigned long long part = *(const unsigned long long*)(od + 2 * j);
            unsigned long long r = mul2(add2(o2[j], part), inv2);
            *(unsigned long long*)(od + 2 * j) = r;
        }
    }
    __syncthreads();

    // coalesced write-out
    for (int i = tid; i < 960; i += 256) {
        int r = i / 15, c4 = i - r * 15;
        float4 v;
        float* vf = (float*)&v;
#pragma unroll
        for (int j = 0; j < 4; j++) {
            int d = c4 * 4 + j;
            int hh = d >= 30;
            vf[j] = sm[hh * 2304 + r * GROWS + (d - 30 * hh)];
        }
        *(float4*)(out + (size_t)(w * NTOK + r) * CDIM + h0 * HD + c4 * 4) = v;
    }
}

// ===========================================================================
extern "C" void kernel_launch(void* const* d_in, const int* in_sizes, int n_in,
                              void* d_out, int out_size)
{
    const float* x      = (const float*)d_in[0];
    const float* mask   = (const float*)d_in[1];
    const float* qkv_w  = (const float*)d_in[2];
    const float* qkv_b  = (const float*)d_in[3];
    const float* proj_w = (const float*)d_in[4];
    const float* proj_b = (const float*)d_in[5];
    const float* rpb    = (const float*)d_in[6];
    float* out = (float*)d_out;

    void* p_qkv = nullptr;
    void* p_att = nullptr;
    cudaGetSymbolAddress(&p_qkv, g_qkv);
    cudaGetSymbolAddress(&p_att, g_att);
    float* qkv = (float*)p_qkv;
    float* att = (float*)p_att;

    const int M = NW * NTOK;                              // 524288
    const int gemm_smem = 3 * GSTAGE_WORDS * sizeof(float);   // 110592
    const int attn_smem = ATT_SMEM_FLOATS * sizeof(float);    // 74248

    static bool attr_set = false;
    if (!attr_set) {
        cudaFuncSetAttribute(mma_gemm_tn,
                             cudaFuncAttributeMaxDynamicSharedMemorySize, gemm_smem);
        cudaFuncSetAttribute(attn_kernel,
                             cudaFuncAttributeMaxDynamicSharedMemorySize, attn_smem);
        attr_set = true;
    }

    // 1) QKV projection: [M,180] @ [540,180]^T + b -> [M,540]
    {
        dim3 grid((3 * CDIM + 127) / 128, M / 128);
        mma_gemm_tn<<<grid, 256, gemm_smem>>>(x, qkv_w, qkv_b, qkv, 3 * CDIM);
    }

    // 2) Attention per (window, head-pair), split-K across thread halves
    {
        dim3 grid(NW, HEADS / 2);
        attn_kernel<<<grid, 256, attn_smem>>>(qkv, mask, rpb, att);
    }

    // 3) Output projection: [M,180] @ [180,180]^T + b -> [M,180]
    {
        dim3 grid((CDIM + 127) / 128, M / 128);
        mma_gemm_tn<<<grid, 256, gemm_smem>>>(att, proj_w, proj_b, out, CDIM);
    }
}

// round 9
// speedup vs baseline: 1.0397x; 1.0397x over previous
#include <cuda_runtime.h>
#include <cuda_bf16.h>
#include <cstdint>

// Problem constants
#define NW   8192
#define NTOK 64
#define CDIM 180
#define HEADS 6
#define HD   30
#define NW_PER_IMG 1024

// Scratch (allocation-guard-safe: __device__ globals)
__device__ float g_qkv[(long long)NW * NTOK * (3 * CDIM)];   // [nW*N, 540]
__device__ float g_att[(long long)NW * NTOK * CDIM];         // [nW*N, 180]

// ===========================================================================
// tf32 helpers
// ===========================================================================
__device__ __forceinline__ float f2tf32(float x) {
    unsigned u;
    asm("cvt.rna.tf32.f32 %0, %1;" : "=r"(u) : "f"(x));
    return __uint_as_float(u);
}

__device__ __forceinline__ void mma_tf32(float d[4], const float a[4], const float b[2]) {
    const unsigned* A = reinterpret_cast<const unsigned*>(a);
    const unsigned* B = reinterpret_cast<const unsigned*>(b);
    asm volatile(
        "mma.sync.aligned.m16n8k8.row.col.f32.tf32.tf32.f32 "
        "{%0,%1,%2,%3},{%4,%5,%6,%7},{%8,%9},{%0,%1,%2,%3};\n"
        : "+f"(d[0]), "+f"(d[1]), "+f"(d[2]), "+f"(d[3])
        : "r"(A[0]), "r"(A[1]), "r"(A[2]), "r"(A[3]), "r"(B[0]), "r"(B[1]));
}

__device__ __forceinline__ void cp_async16(unsigned dst, const void* src, int src_bytes) {
    asm volatile("cp.async.cg.shared.global [%0], [%1], 16, %2;\n"
                 :: "r"(dst), "l"(src), "r"(src_bytes));
}
__device__ __forceinline__ void cp_commit() {
    asm volatile("cp.async.commit_group;\n" ::: "memory");
}
__device__ __forceinline__ void cp_wait1() {
    asm volatile("cp.async.wait_group 1;\n" ::: "memory");
}

// ===========================================================================
// GEMM (TN): C[M,N] = A[M,180] @ B[N,180]^T + bias[N]
// BM=128, BN=128, BK=32, 3-stage cp.async pipeline, 256 threads, tf32 mma.
// Fragments rounded with cvt.rna.tf32 post-LDS for accuracy. (unchanged R6)
// ===========================================================================
#define GROWS 36
#define GSTAGE_WORDS (256 * GROWS)
#define GNITER 6

__global__ __launch_bounds__(256, 2) void mma_gemm_tn(
    const float* __restrict__ A, const float* __restrict__ B,
    const float* __restrict__ bias, float* __restrict__ C, int N)
{
    extern __shared__ float sm[];
    const int tid = threadIdx.x;
    const int row0 = blockIdx.y * 128;
    const int col0 = blockIdx.x * 128;

    const unsigned sbase = (unsigned)__cvta_generic_to_shared(sm);

    auto stage_load = [&](int s, int ki) {
        const int k0 = ki * 32;
        const unsigned stW = sbase + (unsigned)(s * GSTAGE_WORDS) * 4u;
#pragma unroll
        for (int j = 0; j < 8; j++) {
            int idx = tid + j * 256;            // 0..2047
            int r  = (idx & 1023) >> 3;         // row 0..127
            int c4 = idx & 7;
            int gk = k0 + c4 * 4;
            int gkc = gk <= 176 ? gk : 176;
            if (idx < 1024) {
                int bytes = (gk <= 176) ? 16 : 0;
                const float* src = A + (size_t)(row0 + r) * CDIM + gkc;
                cp_async16(stW + (unsigned)(r * GROWS + c4 * 4) * 4u, src, bytes);
            } else {
                int nn = col0 + r;
                int ok = (nn < N) && (gk <= 176);
                const float* src = B + (size_t)(ok ? nn : 0) * CDIM + gkc;
                cp_async16(stW + (unsigned)(128 * GROWS + r * GROWS + c4 * 4) * 4u,
                           src, ok ? 16 : 0);
            }
        }
    };

    stage_load(0, 0); cp_commit();
    stage_load(1, 1); cp_commit();
    cp_wait1();
    __syncthreads();

    const int warp = tid >> 5;
    const int lane = tid & 31;
    const int wm = warp & 1;
    const int wn = warp >> 1;
    const int g = lane >> 2;
    const int t = lane & 3;

    float acc[4][4][4];
#pragma unroll
    for (int mt = 0; mt < 4; mt++)
#pragma unroll
        for (int nt = 0; nt < 4; nt++)
#pragma unroll
            for (int e = 0; e < 4; e++) acc[mt][nt][e] = 0.f;

#pragma unroll 1
    for (int ks = 0; ks < GNITER; ks++) {
        if (ks + 2 < GNITER) stage_load((ks + 2) % 3, ks + 2);
        cp_commit();

        const float* sA = sm + (ks % 3) * GSTAGE_WORDS;
        const float* sB = sA + 128 * GROWS;

#pragma unroll
        for (int step = 0; step < 4; step++) {
            const int kb = step * 8;
            float a[4][4], b[4][2];
#pragma unroll
            for (int mt = 0; mt < 4; mt++) {
                int base = (wm * 64 + mt * 16 + g) * GROWS + kb + t;
                a[mt][0] = f2tf32(sA[base]);
                a[mt][1] = f2tf32(sA[base + 8 * GROWS]);
                a[mt][2] = f2tf32(sA[base + 4]);
                a[mt][3] = f2tf32(sA[base + 8 * GROWS + 4]);
            }
#pragma unroll
            for (int nt = 0; nt < 4; nt++) {
                int bb = (wn * 32 + nt * 8 + g) * GROWS + kb + t;
                b[nt][0] = f2tf32(sB[bb]);
                b[nt][1] = f2tf32(sB[bb + 4]);
            }
#pragma unroll
            for (int mt = 0; mt < 4; mt++)
#pragma unroll
                for (int nt = 0; nt < 4; nt++)
                    mma_tf32(acc[mt][nt], a[mt], b[nt]);
        }
        cp_wait1();
        __syncthreads();
    }

#pragma unroll
    for (int mt = 0; mt < 4; mt++) {
#pragma unroll
        for (int nt = 0; nt < 4; nt++) {
            int row = row0 + wm * 64 + mt * 16 + g;
            int col = col0 + wn * 32 + nt * 8 + 2 * t;
            if (col < N) {
                float b0 = bias[col], b1 = bias[col + 1];
                float2 v0 = make_float2(acc[mt][nt][0] + b0, acc[mt][nt][1] + b1);
                float2 v1 = make_float2(acc[mt][nt][2] + b0, acc[mt][nt][3] + b1);
                *(float2*)(C + (size_t)row * N + col) = v0;
                *(float2*)(C + (size_t)(row + 8) * N + col) = v1;
            }
        }
    }
}

// ===========================================================================
// MMA attention: one block per (window, head). 128 threads = 4 warps,
// warp ws owns query rows [ws*16, ws*16+16).
//   S(64x64)  = Qs @ K^T   via tf32 m16n8k8 (K-dim = hd padded to 32)
//   P = exp(S + bias + mask)  (no-max softmax; scores are small)
//   O(64x30)  = P @ V      via tf32 m16n8k8 (K-dim = 64, N = 32 padded)
// Q/K/V tf32-rounded at staging; P tf32-rounded before its smem store.
// smem (floats):
//   sQ[64][36] @0, sK[64][36] @2304, sV[64][36] @4608,
//   sBias[64][68] @6912 (rpb+mask combined), sP[4][16][68] @11264
// total 15616 floats = 62464 B
// ===========================================================================
#define ASM_K 2304
#define ASM_V 4608
#define ASM_B 6912
#define ASM_P 11264
#define ATT_SMEM_FLOATS 15616

__global__ __launch_bounds__(128) void attn_mma_kernel(
    const float* __restrict__ qkv, const float* __restrict__ mask,
    const float* __restrict__ rpb, float* __restrict__ out)
{
    extern __shared__ float sm[];
    const int w = blockIdx.x;
    const int h = blockIdx.y;
    const int tid = threadIdx.x;
    const int ws = tid >> 5;
    const int lane = tid & 31;
    const int g = lane >> 2;
    const int t = lane & 3;

    const float scale = rsqrtf((float)HD);

    // ---- stage q/k/v (tf32-rounded, q pre-scaled), float2 granularity ----
    for (int i = tid; i < 2880; i += 128) {
        int arr = i / 960;                     // 0=q 1=k 2=v
        int rem = i - arr * 960;
        int r = rem / 15, c2 = rem - r * 15;
        float2 v = *(const float2*)(qkv + (size_t)(w * NTOK + r) * (3 * CDIM)
                                    + arr * CDIM + h * HD + c2 * 2);
        if (arr == 0) { v.x *= scale; v.y *= scale; }
        float* dst = sm + arr * 2304 + r * 36 + c2 * 2;
        dst[0] = f2tf32(v.x);
        dst[1] = f2tf32(v.y);
    }
    // zero pad d=30,31 for q/k/v
    for (int i = tid; i < 384; i += 128) {
        int arr = i >> 7, rem = i & 127;
        int r = rem >> 1, d = 30 + (rem & 1);
        sm[arr * 2304 + r * 36 + d] = 0.f;
    }
    // ---- combined bias tile: rpb_h(r,c) + mask(wi,r,c) ----
    {
        const int wi = w & (NW_PER_IMG - 1);
        const float4* mb = (const float4*)(mask + (size_t)wi * NTOK * NTOK);
        for (int i = tid; i < 1024; i += 128) {
            float4 mv = mb[i];
            int r = i >> 4, c0 = (i & 15) * 4;
            int i1 = r >> 3, j1 = r & 7;
            float o[4];
#pragma unroll
            for (int j = 0; j < 4; j++) {
                int c = c0 + j;
                int idx = (i1 - (c >> 3) + 7) * 15 + (j1 - (c & 7) + 7);
                o[j] = rpb[idx * HEADS + h] + ((const float*)&mv)[j];
            }
            *(float4*)(sm + ASM_B + r * 68 + c0) = make_float4(o[0], o[1], o[2], o[3]);
        }
    }
    __syncthreads();

    const int row_g = ws * 16 + g;

    // ---- Q a-fragments (4 k-chunks of 8) ----
    float qa[4][4];
#pragma unroll
    for (int kc = 0; kc < 4; kc++) {
        qa[kc][0] = sm[row_g * 36 + kc * 8 + t];
        qa[kc][1] = sm[(row_g + 8) * 36 + kc * 8 + t];
        qa[kc][2] = sm[row_g * 36 + kc * 8 + t + 4];
        qa[kc][3] = sm[(row_g + 8) * 36 + kc * 8 + t + 4];
    }

    // ---- scores + exp + P store ----
    float rs0 = 0.f, rs1 = 0.f;
    float* sPw = sm + ASM_P + ws * 1088;
#pragma unroll
    for (int nt = 0; nt < 8; nt++) {
        float acc[4] = {0.f, 0.f, 0.f, 0.f};
#pragma unroll
        for (int kc = 0; kc < 4; kc++) {
            float b[2];
            b[0] = sm[ASM_K + (nt * 8 + g) * 36 + kc * 8 + t];
            b[1] = sm[ASM_K + (nt * 8 + g) * 36 + kc * 8 + t + 4];
            mma_tf32(acc, qa[kc], b);
        }
        float2 b0 = *(const float2*)(sm + ASM_B + row_g * 68 + nt * 8 + 2 * t);
        float2 b1 = *(const float2*)(sm + ASM_B + (row_g + 8) * 68 + nt * 8 + 2 * t);
        float p0 = f2tf32(__expf(acc[0] + b0.x));
        float p1 = f2tf32(__expf(acc[1] + b0.y));
        float p2 = f2tf32(__expf(acc[2] + b1.x));
        float p3 = f2tf32(__expf(acc[3] + b1.y));
        rs0 += p0 + p1;
        rs1 += p2 + p3;
        *(float2*)(sPw + g * 68 + nt * 8 + 2 * t) = make_float2(p0, p1);
        *(float2*)(sPw + (g + 8) * 68 + nt * 8 + 2 * t) = make_float2(p2, p3);
    }
    // row sums: reduce over t within each quad
    rs0 += __shfl_xor_sync(0xffffffffu, rs0, 1);
    rs0 += __shfl_xor_sync(0xffffffffu, rs0, 2);
    rs1 += __shfl_xor_sync(0xffffffffu, rs1, 1);
    rs1 += __shfl_xor_sync(0xffffffffu, rs1, 2);
    __syncwarp();

    // ---- PV: O(16x32) per warp ----
    float oacc[4][4];
#pragma unroll
    for (int nd = 0; nd < 4; nd++)
#pragma unroll
        for (int e = 0; e < 4; e++) oacc[nd][e] = 0.f;

#pragma unroll
    for (int kc = 0; kc < 8; kc++) {
        float a[4];
        a[0] = sPw[g * 68 + kc * 8 + t];
        a[1] = sPw[(g + 8) * 68 + kc * 8 + t];
        a[2] = sPw[g * 68 + kc * 8 + t + 4];
        a[3] = sPw[(g + 8) * 68 + kc * 8 + t + 4];
#pragma unroll
        for (int nd = 0; nd < 4; nd++) {
            float b[2];
            b[0] = sm[ASM_V + (kc * 8 + t) * 36 + nd * 8 + g];
            b[1] = sm[ASM_V + (kc * 8 + t + 4) * 36 + nd * 8 + g];
            mma_tf32(oacc[nd], a, b);
        }
    }

    // ---- normalize + write out ----
    const float inv0 = 1.f / rs0;
    const float inv1 = 1.f / rs1;
#pragma unroll
    for (int nd = 0; nd < 4; nd++) {
        int d = nd * 8 + 2 * t;
        if (d < HD) {
            float2 v0 = make_float2(oacc[nd][0] * inv0, oacc[nd][1] * inv0);
            float2 v1 = make_float2(oacc[nd][2] * inv1, oacc[nd][3] * inv1);
            *(float2*)(out + (size_t)(w * NTOK + row_g) * CDIM + h * HD + d) = v0;
            *(float2*)(out + (size_t)(w * NTOK + row_g + 8) * CDIM + h * HD + d) = v1;
        }
    }
}

// ===========================================================================
extern "C" void kernel_launch(void* const* d_in, const int* in_sizes, int n_in,
                              void* d_out, int out_size)
{
    const float* x      = (const float*)d_in[0];
    const float* mask   = (const float*)d_in[1];
    const float* qkv_w  = (const float*)d_in[2];
    const float* qkv_b  = (const float*)d_in[3];
    const float* proj_w = (const float*)d_in[4];
    const float* proj_b = (const float*)d_in[5];
    const float* rpb    = (const float*)d_in[6];
    float* out = (float*)d_out;

    void* p_qkv = nullptr;
    void* p_att = nullptr;
    cudaGetSymbolAddress(&p_qkv, g_qkv);
    cudaGetSymbolAddress(&p_att, g_att);
    float* qkv = (float*)p_qkv;
    float* att = (float*)p_att;

    const int M = NW * NTOK;                                  // 524288
    const int gemm_smem = 3 * GSTAGE_WORDS * sizeof(float);   // 110592
    const int attn_smem = ATT_SMEM_FLOATS * sizeof(float);    // 62464

    static bool attr_set = false;
    if (!attr_set) {
        cudaFuncSetAttribute(mma_gemm_tn,
                             cudaFuncAttributeMaxDynamicSharedMemorySize, gemm_smem);
        cudaFuncSetAttribute(attn_mma_kernel,
                             cudaFuncAttributeMaxDynamicSharedMemorySize, attn_smem);
        attr_set = true;
    }

    // 1) QKV projection: [M,180] @ [540,180]^T + b -> [M,540]
    {
        dim3 grid((3 * CDIM + 127) / 128, M / 128);
        mma_gemm_tn<<<grid, 256, gemm_smem>>>(x, qkv_w, qkv_b, qkv, 3 * CDIM);
    }

    // 2) MMA attention per (window, head)
    {
        dim3 grid(NW, HEADS);
        attn_mma_kernel<<<grid, 128, attn_smem>>>(qkv, mask, rpb, att);
    }

    // 3) Output projection: [M,180] @ [180,180]^T + b -> [M,180]
    {
        dim3 grid((CDIM + 127) / 128, M / 128);
        mma_gemm_tn<<<grid, 256, gemm_smem>>>(att, proj_w, proj_b, out, CDIM);
    }
}

// round 11
// speedup vs baseline: 1.1658x; 1.1213x over previous
#include <cuda_runtime.h>
#include <cuda_bf16.h>
#include <cstdint>

// Problem constants
#define NW   8192
#define NTOK 64
#define CDIM 180
#define HEADS 6
#define HD   30
#define NW_PER_IMG 1024

// Scratch (allocation-guard-safe: __device__ globals)
__device__ float g_qkv[(long long)NW * NTOK * (3 * CDIM)];   // [nW*N, 540]
__device__ float g_att[(long long)NW * NTOK * CDIM];         // [nW*N, 180]
__device__ float g_bias6[HEADS * NTOK * NTOK];               // rpb expanded

// ===========================================================================
// tf32 helpers
// ===========================================================================
__device__ __forceinline__ float f2tf32(float x) {
    unsigned u;
    asm("cvt.rna.tf32.f32 %0, %1;" : "=r"(u) : "f"(x));
    return __uint_as_float(u);
}

__device__ __forceinline__ void mma_tf32(float d[4], const float a[4], const float b[2]) {
    const unsigned* A = reinterpret_cast<const unsigned*>(a);
    const unsigned* B = reinterpret_cast<const unsigned*>(b);
    asm volatile(
        "mma.sync.aligned.m16n8k8.row.col.f32.tf32.tf32.f32 "
        "{%0,%1,%2,%3},{%4,%5,%6,%7},{%8,%9},{%0,%1,%2,%3};\n"
        : "+f"(d[0]), "+f"(d[1]), "+f"(d[2]), "+f"(d[3])
        : "r"(A[0]), "r"(A[1]), "r"(A[2]), "r"(A[3]), "r"(B[0]), "r"(B[1]));
}

__device__ __forceinline__ void cp_async16(unsigned dst, const void* src, int src_bytes) {
    asm volatile("cp.async.cg.shared.global [%0], [%1], 16, %2;\n"
                 :: "r"(dst), "l"(src), "r"(src_bytes));
}
__device__ __forceinline__ void cp_commit() {
    asm volatile("cp.async.commit_group;\n" ::: "memory");
}
__device__ __forceinline__ void cp_wait1() {
    asm volatile("cp.async.wait_group 1;\n" ::: "memory");
}

// ===========================================================================
// GEMM (TN): C[M,N] = A[M,180] @ B[N,180]^T + bias[N]   (unchanged from R6/R9)
// ===========================================================================
#define GROWS 36
#define GSTAGE_WORDS (256 * GROWS)
#define GNITER 6

__global__ __launch_bounds__(256, 2) void mma_gemm_tn(
    const float* __restrict__ A, const float* __restrict__ B,
    const float* __restrict__ bias, float* __restrict__ C, int N)
{
    extern __shared__ float sm[];
    const int tid = threadIdx.x;
    const int row0 = blockIdx.y * 128;
    const int col0 = blockIdx.x * 128;

    const unsigned sbase = (unsigned)__cvta_generic_to_shared(sm);

    auto stage_load = [&](int s, int ki) {
        const int k0 = ki * 32;
        const unsigned stW = sbase + (unsigned)(s * GSTAGE_WORDS) * 4u;
#pragma unroll
        for (int j = 0; j < 8; j++) {
            int idx = tid + j * 256;
            int r  = (idx & 1023) >> 3;
            int c4 = idx & 7;
            int gk = k0 + c4 * 4;
            int gkc = gk <= 176 ? gk : 176;
            if (idx < 1024) {
                int bytes = (gk <= 176) ? 16 : 0;
                const float* src = A + (size_t)(row0 + r) * CDIM + gkc;
                cp_async16(stW + (unsigned)(r * GROWS + c4 * 4) * 4u, src, bytes);
            } else {
                int nn = col0 + r;
                int ok = (nn < N) && (gk <= 176);
                const float* src = B + (size_t)(ok ? nn : 0) * CDIM + gkc;
                cp_async16(stW + (unsigned)(128 * GROWS + r * GROWS + c4 * 4) * 4u,
                           src, ok ? 16 : 0);
            }
        }
    };

    stage_load(0, 0); cp_commit();
    stage_load(1, 1); cp_commit();
    cp_wait1();
    __syncthreads();

    const int warp = tid >> 5;
    const int lane = tid & 31;
    const int wm = warp & 1;
    const int wn = warp >> 1;
    const int g = lane >> 2;
    const int t = lane & 3;

    float acc[4][4][4];
#pragma unroll
    for (int mt = 0; mt < 4; mt++)
#pragma unroll
        for (int nt = 0; nt < 4; nt++)
#pragma unroll
            for (int e = 0; e < 4; e++) acc[mt][nt][e] = 0.f;

#pragma unroll 1
    for (int ks = 0; ks < GNITER; ks++) {
        if (ks + 2 < GNITER) stage_load((ks + 2) % 3, ks + 2);
        cp_commit();

        const float* sA = sm + (ks % 3) * GSTAGE_WORDS;
        const float* sB = sA + 128 * GROWS;

#pragma unroll
        for (int step = 0; step < 4; step++) {
            const int kb = step * 8;
            float a[4][4], b[4][2];
#pragma unroll
            for (int mt = 0; mt < 4; mt++) {
                int base = (wm * 64 + mt * 16 + g) * GROWS + kb + t;
                a[mt][0] = f2tf32(sA[base]);
                a[mt][1] = f2tf32(sA[base + 8 * GROWS]);
                a[mt][2] = f2tf32(sA[base + 4]);
                a[mt][3] = f2tf32(sA[base + 8 * GROWS + 4]);
            }
#pragma unroll
            for (int nt = 0; nt < 4; nt++) {
                int bb = (wn * 32 + nt * 8 + g) * GROWS + kb + t;
                b[nt][0] = f2tf32(sB[bb]);
                b[nt][1] = f2tf32(sB[bb + 4]);
            }
#pragma unroll
            for (int mt = 0; mt < 4; mt++)
#pragma unroll
                for (int nt = 0; nt < 4; nt++)
                    mma_tf32(acc[mt][nt], a[mt], b[nt]);
        }
        cp_wait1();
        __syncthreads();
    }

#pragma unroll
    for (int mt = 0; mt < 4; mt++) {
#pragma unroll
        for (int nt = 0; nt < 4; nt++) {
            int row = row0 + wm * 64 + mt * 16 + g;
            int col = col0 + wn * 32 + nt * 8 + 2 * t;
            if (col < N) {
                float b0 = bias[col], b1 = bias[col + 1];
                float2 v0 = make_float2(acc[mt][nt][0] + b0, acc[mt][nt][1] + b1);
                float2 v1 = make_float2(acc[mt][nt][2] + b0, acc[mt][nt][3] + b1);
                *(float2*)(C + (size_t)row * N + col) = v0;
                *(float2*)(C + (size_t)(row + 8) * N + col) = v1;
            }
        }
    }
}

// ===========================================================================
// One-shot RPB expansion: g_bias6[h][r][c] = rpb[rpi(r,c)*HEADS + h]
// ===========================================================================
__global__ void bias_expand_kernel(const float* __restrict__ rpb)
{
    const int h = blockIdx.x;
    for (int i = threadIdx.x; i < NTOK * NTOK; i += blockDim.x) {
        int r = i >> 6, c = i & 63;
        int idx = ((r >> 3) - (c >> 3) + 7) * 15 + ((r & 7) - (c & 7) + 7);
        g_bias6[h * NTOK * NTOK + i] = rpb[idx * HEADS + h];
    }
}

// ===========================================================================
// MMA attention: one block per (window, head). 128 threads = 4 warps,
// warp ws owns query rows [ws*16, ws*16+16).
//   S = Qs@K^T (tf32 mma), P = exp(S + bias6 + mask), O = P@V (tf32 mma).
// smem (floats):
//   sQ[64][36] @0, sK[64][36] @2304, sV[64][36] @4608,
//   sBM[64][68] @6912  -- bias6+mask tile; per-warp 16-row stripes are
//                         overwritten with P after bias values move to regs.
// total 11264 floats = 45056 B -> 5 CTAs/SM.
// ===========================================================================
#define ASM_K 2304
#define ASM_V 4608
#define ASM_B 6912
#define ATT_SMEM_FLOATS 11264

__global__ __launch_bounds__(128) void attn_mma_kernel(
    const float* __restrict__ qkv, const float* __restrict__ mask,
    float* __restrict__ out)
{
    extern __shared__ float sm[];
    const int w = blockIdx.x;
    const int h = blockIdx.y;
    const int tid = threadIdx.x;
    const int ws = tid >> 5;
    const int lane = tid & 31;
    const int g = lane >> 2;
    const int t = lane & 3;

    const float scale = rsqrtf((float)HD);

    // ---- stage q/k/v (tf32-rounded, q pre-scaled), float2 granularity ----
    for (int i = tid; i < 2880; i += 128) {
        int arr = i / 960;                     // 0=q 1=k 2=v
        int rem = i - arr * 960;
        int r = rem / 15, c2 = rem - r * 15;
        float2 v = *(const float2*)(qkv + (size_t)(w * NTOK + r) * (3 * CDIM)
                                    + arr * CDIM + h * HD + c2 * 2);
        if (arr == 0) { v.x *= scale; v.y *= scale; }
        float* dst = sm + arr * 2304 + r * 36 + c2 * 2;
        dst[0] = f2tf32(v.x);
        dst[1] = f2tf32(v.y);
    }
    // zero pad d=30,31 for q/k/v
    for (int i = tid; i < 384; i += 128) {
        int arr = i >> 7, rem = i & 127;
        int r = rem >> 1, d = 30 + (rem & 1);
        sm[arr * 2304 + r * 36 + d] = 0.f;
    }
    // ---- combined bias tile: bias6[h] + mask[wi], both coalesced float4 ----
    {
        const int wi = w & (NW_PER_IMG - 1);
        const float4* mb = (const float4*)(mask + (size_t)wi * NTOK * NTOK);
        const float4* bb = (const float4*)(g_bias6 + h * NTOK * NTOK);
        for (int i = tid; i < 1024; i += 128) {
            float4 mv = mb[i];
            float4 bv = bb[i];
            int r = i >> 4, c0 = (i & 15) * 4;
            *(float4*)(sm + ASM_B + r * 68 + c0) =
                make_float4(mv.x + bv.x, mv.y + bv.y, mv.z + bv.z, mv.w + bv.w);
        }
    }
    __syncthreads();

    const int row_g = ws * 16 + g;

    // ---- Q a-fragments (4 k-chunks of 8) ----
    float qa[4][4];
#pragma unroll
    for (int kc = 0; kc < 4; kc++) {
        qa[kc][0] = sm[row_g * 36 + kc * 8 + t];
        qa[kc][1] = sm[(row_g + 8) * 36 + kc * 8 + t];
        qa[kc][2] = sm[row_g * 36 + kc * 8 + t + 4];
        qa[kc][3] = sm[(row_g + 8) * 36 + kc * 8 + t + 4];
    }

    // ---- preload this thread's bias+mask values into regs (own stripe) ----
    float2 bia0[8], bia1[8];
#pragma unroll
    for (int nt = 0; nt < 8; nt++) {
        bia0[nt] = *(const float2*)(sm + ASM_B + row_g * 68 + nt * 8 + 2 * t);
        bia1[nt] = *(const float2*)(sm + ASM_B + (row_g + 8) * 68 + nt * 8 + 2 * t);
    }
    __syncwarp();   // all lanes' bias reads complete before P overwrites stripe

    // ---- scores + exp + P store (into own 16-row stripe of sBM) ----
    float rs0 = 0.f, rs1 = 0.f;
    float* sPw = sm + ASM_B + ws * 16 * 68;
#pragma unroll
    for (int nt = 0; nt < 8; nt++) {
        float acc[4] = {0.f, 0.f, 0.f, 0.f};
#pragma unroll
        for (int kc = 0; kc < 4; kc++) {
            float b[2];
            b[0] = sm[ASM_K + (nt * 8 + g) * 36 + kc * 8 + t];
            b[1] = sm[ASM_K + (nt * 8 + g) * 36 + kc * 8 + t + 4];
            mma_tf32(acc, qa[kc], b);
        }
        float p0 = f2tf32(__expf(acc[0] + bia0[nt].x));
        float p1 = f2tf32(__expf(acc[1] + bia0[nt].y));
        float p2 = f2tf32(__expf(acc[2] + bia1[nt].x));
        float p3 = f2tf32(__expf(acc[3] + bia1[nt].y));
        rs0 += p0 + p1;
        rs1 += p2 + p3;
        *(float2*)(sPw + g * 68 + nt * 8 + 2 * t) = make_float2(p0, p1);
        *(float2*)(sPw + (g + 8) * 68 + nt * 8 + 2 * t) = make_float2(p2, p3);
    }
    // row sums: reduce over t within each quad
    rs0 += __shfl_xor_sync(0xffffffffu, rs0, 1);
    rs0 += __shfl_xor_sync(0xffffffffu, rs0, 2);
    rs1 += __shfl_xor_sync(0xffffffffu, rs1, 1);
    rs1 += __shfl_xor_sync(0xffffffffu, rs1, 2);
    __syncwarp();

    // ---- PV: O(16x32) per warp ----
    float oacc[4][4];
#pragma unroll
    for (int nd = 0; nd < 4; nd++)
#pragma unroll
        for (int e = 0; e < 4; e++) oacc[nd][e] = 0.f;

#pragma unroll
    for (int kc = 0; kc < 8; kc++) {
        float a[4];
        a[0] = sPw[g * 68 + kc * 8 + t];
        a[1] = sPw[(g + 8) * 68 + kc * 8 + t];
        a[2] = sPw[g * 68 + kc * 8 + t + 4];
        a[3] = sPw[(g + 8) * 68 + kc * 8 + t + 4];
#pragma unroll
        for (int nd = 0; nd < 4; nd++) {
            float b[2];
            b[0] = sm[ASM_V + (kc * 8 + t) * 36 + nd * 8 + g];
            b[1] = sm[ASM_V + (kc * 8 + t + 4) * 36 + nd * 8 + g];
            mma_tf32(oacc[nd], a, b);
        }
    }

    // ---- normalize + write out ----
    const float inv0 = 1.f / rs0;
    const float inv1 = 1.f / rs1;
#pragma unroll
    for (int nd = 0; nd < 4; nd++) {
        int d = nd * 8 + 2 * t;
        if (d < HD) {
            float2 v0 = make_float2(oacc[nd][0] * inv0, oacc[nd][1] * inv0);
            float2 v1 = make_float2(oacc[nd][2] * inv1, oacc[nd][3] * inv1);
            *(float2*)(out + (size_t)(w * NTOK + row_g) * CDIM + h * HD + d) = v0;
            *(float2*)(out + (size_t)(w * NTOK + row_g + 8) * CDIM + h * HD + d) = v1;
        }
    }
}

// ===========================================================================
extern "C" void kernel_launch(void* const* d_in, const int* in_sizes, int n_in,
                              void* d_out, int out_size)
{
    const float* x      = (const float*)d_in[0];
    const float* mask   = (const float*)d_in[1];
    const float* qkv_w  = (const float*)d_in[2];
    const float* qkv_b  = (const float*)d_in[3];
    const float* proj_w = (const float*)d_in[4];
    const float* proj_b = (const float*)d_in[5];
    const float* rpb    = (const float*)d_in[6];
    float* out = (float*)d_out;

    void* p_qkv = nullptr;
    void* p_att = nullptr;
    cudaGetSymbolAddress(&p_qkv, g_qkv);
    cudaGetSymbolAddress(&p_att, g_att);
    float* qkv = (float*)p_qkv;
    float* att = (float*)p_att;

    const int M = NW * NTOK;                                  // 524288
    const int gemm_smem = 3 * GSTAGE_WORDS * sizeof(float);   // 110592
    const int attn_smem = ATT_SMEM_FLOATS * sizeof(float);    // 45056

    static bool attr_set = false;
    if (!attr_set) {
        cudaFuncSetAttribute(mma_gemm_tn,
                             cudaFuncAttributeMaxDynamicSharedMemorySize, gemm_smem);
        cudaFuncSetAttribute(attn_mma_kernel,
                             cudaFuncAttributeMaxDynamicSharedMemorySize, attn_smem);
        attr_set = true;
    }

    // 0) Expand RPB once (independent of QKV; tiny)
    bias_expand_kernel<<<HEADS, 256>>>(rpb);

    // 1) QKV projection: [M,180] @ [540,180]^T + b -> [M,540]
    {
        dim3 grid((3 * CDIM + 127) / 128, M / 128);
        mma_gemm_tn<<<grid, 256, gemm_smem>>>(x, qkv_w, qkv_b, qkv, 3 * CDIM);
    }

    // 2) MMA attention per (window, head)
    {
        dim3 grid(NW, HEADS);
        attn_mma_kernel<<<grid, 128, attn_smem>>>(qkv, mask, att);
    }

    // 3) Output projection: [M,180] @ [180,180]^T + b -> [M,180]
    {
        dim3 grid((CDIM + 127) / 128, M / 128);
        mma_gemm_tn<<<grid, 256, gemm_smem>>>(att, proj_w, proj_b, out, CDIM);
    }
}

// round 13
// speedup vs baseline: 1.3186x; 1.1311x over previous
#include <cuda_runtime.h>
#include <cuda_bf16.h>
#include <cstdint>

// Problem constants
#define NW   8192
#define NTOK 64
#define CDIM 180
#define HEADS 6
#define HD   30
#define NW_PER_IMG 1024

// Scratch (allocation-guard-safe: __device__ globals)
__device__ float g_qkv[(long long)NW * NTOK * (3 * CDIM)];   // [nW*N, 540]
__device__ float g_att[(long long)NW * NTOK * CDIM];         // rounded-x, then attn out
__device__ float g_bias6[HEADS * NTOK * NTOK];               // rpb expanded
__device__ float g_wq[3 * CDIM * CDIM];                      // rounded qkv_w
__device__ float g_wp[CDIM * CDIM];                          // rounded proj_w

// ===========================================================================
// tf32 helpers
// ===========================================================================
__device__ __forceinline__ float f2tf32(float x) {
    unsigned u;
    asm("cvt.rna.tf32.f32 %0, %1;" : "=r"(u) : "f"(x));
    return __uint_as_float(u);
}

__device__ __forceinline__ void mma_tf32(float d[4], const float a[4], const float b[2]) {
    const unsigned* A = reinterpret_cast<const unsigned*>(a);
    const unsigned* B = reinterpret_cast<const unsigned*>(b);
    asm volatile(
        "mma.sync.aligned.m16n8k8.row.col.f32.tf32.tf32.f32 "
        "{%0,%1,%2,%3},{%4,%5,%6,%7},{%8,%9},{%0,%1,%2,%3};\n"
        : "+f"(d[0]), "+f"(d[1]), "+f"(d[2]), "+f"(d[3])
        : "r"(A[0]), "r"(A[1]), "r"(A[2]), "r"(A[3]), "r"(B[0]), "r"(B[1]));
}

__device__ __forceinline__ void cp_async16(unsigned dst, const void* src, int src_bytes) {
    asm volatile("cp.async.cg.shared.global [%0], [%1], 16, %2;\n"
                 :: "r"(dst), "l"(src), "r"(src_bytes));
}
__device__ __forceinline__ void cp_commit() {
    asm volatile("cp.async.commit_group;\n" ::: "memory");
}
__device__ __forceinline__ void cp_wait1() {
    asm volatile("cp.async.wait_group 1;\n" ::: "memory");
}

// ===========================================================================
// Pre-round: out[i] = tf32_rna(in[i]), float4 grid-stride
// ===========================================================================
__global__ void round_kernel(const float* __restrict__ in, float* __restrict__ out, int n4)
{
    int i = blockIdx.x * blockDim.x + threadIdx.x;
    for (; i < n4; i += gridDim.x * blockDim.x) {
        float4 v = ((const float4*)in)[i];
        v.x = f2tf32(v.x); v.y = f2tf32(v.y);
        v.z = f2tf32(v.z); v.w = f2tf32(v.w);
        ((float4*)out)[i] = v;
    }
}

// ===========================================================================
// GEMM (TN): C[M,N] = A[M,180] @ B[N,180]^T + bias[N]
// Inputs pre-rounded to tf32 -> no cvt in mainloop.
// ===========================================================================
#define GROWS 36
#define GSTAGE_WORDS (256 * GROWS)
#define GNITER 6

__global__ __launch_bounds__(256, 2) void mma_gemm_tn(
    const float* __restrict__ A, const float* __restrict__ B,
    const float* __restrict__ bias, float* __restrict__ C, int N)
{
    extern __shared__ float sm[];
    const int tid = threadIdx.x;
    const int row0 = blockIdx.y * 128;
    const int col0 = blockIdx.x * 128;

    const unsigned sbase = (unsigned)__cvta_generic_to_shared(sm);

    auto stage_load = [&](int s, int ki) {
        const int k0 = ki * 32;
        const unsigned stW = sbase + (unsigned)(s * GSTAGE_WORDS) * 4u;
#pragma unroll
        for (int j = 0; j < 8; j++) {
            int idx = tid + j * 256;
            int r  = (idx & 1023) >> 3;
            int c4 = idx & 7;
            int gk = k0 + c4 * 4;
            int gkc = gk <= 176 ? gk : 176;
            if (idx < 1024) {
                int bytes = (gk <= 176) ? 16 : 0;
                const float* src = A + (size_t)(row0 + r) * CDIM + gkc;
                cp_async16(stW + (unsigned)(r * GROWS + c4 * 4) * 4u, src, bytes);
            } else {
                int nn = col0 + r;
                int ok = (nn < N) && (gk <= 176);
                const float* src = B + (size_t)(ok ? nn : 0) * CDIM + gkc;
                cp_async16(stW + (unsigned)(128 * GROWS + r * GROWS + c4 * 4) * 4u,
                           src, ok ? 16 : 0);
            }
        }
    };

    stage_load(0, 0); cp_commit();
    stage_load(1, 1); cp_commit();
    cp_wait1();
    __syncthreads();

    const int warp = tid >> 5;
    const int lane = tid & 31;
    const int wm = warp & 1;
    const int wn = warp >> 1;
    const int g = lane >> 2;
    const int t = lane & 3;

    float acc[4][4][4];
#pragma unroll
    for (int mt = 0; mt < 4; mt++)
#pragma unroll
        for (int nt = 0; nt < 4; nt++)
#pragma unroll
            for (int e = 0; e < 4; e++) acc[mt][nt][e] = 0.f;

#pragma unroll 1
    for (int ks = 0; ks < GNITER; ks++) {
        if (ks + 2 < GNITER) stage_load((ks + 2) % 3, ks + 2);
        cp_commit();

        const float* sA = sm + (ks % 3) * GSTAGE_WORDS;
        const float* sB = sA + 128 * GROWS;

#pragma unroll
        for (int step = 0; step < 4; step++) {
            const int kb = step * 8;
            float a[4][4], b[4][2];
#pragma unroll
            for (int mt = 0; mt < 4; mt++) {
                int base = (wm * 64 + mt * 16 + g) * GROWS + kb + t;
                a[mt][0] = sA[base];
                a[mt][1] = sA[base + 8 * GROWS];
                a[mt][2] = sA[base + 4];
                a[mt][3] = sA[base + 8 * GROWS + 4];
            }
#pragma unroll
            for (int nt = 0; nt < 4; nt++) {
                int bb = (wn * 32 + nt * 8 + g) * GROWS + kb + t;
                b[nt][0] = sB[bb];
                b[nt][1] = sB[bb + 4];
            }
#pragma unroll
            for (int mt = 0; mt < 4; mt++)
#pragma unroll
                for (int nt = 0; nt < 4; nt++)
                    mma_tf32(acc[mt][nt], a[mt], b[nt]);
        }
        cp_wait1();
        __syncthreads();
    }

#pragma unroll
    for (int mt = 0; mt < 4; mt++) {
#pragma unroll
        for (int nt = 0; nt < 4; nt++) {
            int row = row0 + wm * 64 + mt * 16 + g;
            int col = col0 + wn * 32 + nt * 8 + 2 * t;
            if (col < N) {
                float b0 = bias[col], b1 = bias[col + 1];
                float2 v0 = make_float2(acc[mt][nt][0] + b0, acc[mt][nt][1] + b1);
                float2 v1 = make_float2(acc[mt][nt][2] + b0, acc[mt][nt][3] + b1);
                *(float2*)(C + (size_t)row * N + col) = v0;
                *(float2*)(C + (size_t)(row + 8) * N + col) = v1;
            }
        }
    }
}

// ===========================================================================
// One-shot RPB expansion: g_bias6[h][r][c] = rpb[rpi(r,c)*HEADS + h]
// ===========================================================================
__global__ void bias_expand_kernel(const float* __restrict__ rpb)
{
    const int h = blockIdx.x;
    for (int i = threadIdx.x; i < NTOK * NTOK; i += blockDim.x) {
        int r = i >> 6, c = i & 63;
        int idx = ((r >> 3) - (c >> 3) + 7) * 15 + ((r & 7) - (c & 7) + 7);
        g_bias6[h * NTOK * NTOK + i] = rpb[idx * HEADS + h];
    }
}

// ===========================================================================
// MMA attention. 1D grid, wi-major block order: all 48 blocks (8 imgs x 6
// heads) sharing one mask tile are adjacent -> mask stays L2-resident.
// Output written tf32-rounded (feeds proj GEMM directly).
// smem: sQ[64][36] @0, sK @2304, sV @4608, sBM[64][68] @6912 (bias+mask,
// stripes reused for P). total 11264 floats = 45056 B -> 5 CTAs/SM.
// ===========================================================================
#define ASM_K 2304
#define ASM_V 4608
#define ASM_B 6912
#define ATT_SMEM_FLOATS 11264

__global__ __launch_bounds__(128) void attn_mma_kernel(
    const float* __restrict__ qkv, const float* __restrict__ mask,
    float* __restrict__ out)
{
    extern __shared__ float sm[];
    // block remap: b -> (wi, img, h), wi slowest
    const int b = blockIdx.x;
    const int wi = b / (8 * HEADS);
    const int sub = b - wi * (8 * HEADS);
    const int img = sub / HEADS;
    const int h = sub - img * HEADS;
    const int w = img * NW_PER_IMG + wi;

    const int tid = threadIdx.x;
    const int ws = tid >> 5;
    const int lane = tid & 31;
    const int g = lane >> 2;
    const int t = lane & 3;

    const float scale = rsqrtf((float)HD);

    // ---- stage q/k/v (tf32-rounded, q pre-scaled), float2 granularity ----
    for (int i = tid; i < 2880; i += 128) {
        int arr = i / 960;                     // 0=q 1=k 2=v
        int rem = i - arr * 960;
        int r = rem / 15, c2 = rem - r * 15;
        float2 v = *(const float2*)(qkv + (size_t)(w * NTOK + r) * (3 * CDIM)
                                    + arr * CDIM + h * HD + c2 * 2);
        if (arr == 0) { v.x *= scale; v.y *= scale; }
        float* dst = sm + arr * 2304 + r * 36 + c2 * 2;
        dst[0] = f2tf32(v.x);
        dst[1] = f2tf32(v.y);
    }
    // zero pad d=30,31 for q/k/v
    for (int i = tid; i < 384; i += 128) {
        int arr = i >> 7, rem = i & 127;
        int r = rem >> 1, d = 30 + (rem & 1);
        sm[arr * 2304 + r * 36 + d] = 0.f;
    }
    // ---- combined bias tile: bias6[h] + mask[wi], both coalesced float4 ----
    {
        const float4* mb = (const float4*)(mask + (size_t)wi * NTOK * NTOK);
        const float4* bb = (const float4*)(g_bias6 + h * NTOK * NTOK);
        for (int i = tid; i < 1024; i += 128) {
            float4 mv = mb[i];
            float4 bv = bb[i];
            int r = i >> 4, c0 = (i & 15) * 4;
            *(float4*)(sm + ASM_B + r * 68 + c0) =
                make_float4(mv.x + bv.x, mv.y + bv.y, mv.z + bv.z, mv.w + bv.w);
        }
    }
    __syncthreads();

    const int row_g = ws * 16 + g;

    // ---- Q a-fragments (4 k-chunks of 8) ----
    float qa[4][4];
#pragma unroll
    for (int kc = 0; kc < 4; kc++) {
        qa[kc][0] = sm[row_g * 36 + kc * 8 + t];
        qa[kc][1] = sm[(row_g + 8) * 36 + kc * 8 + t];
        qa[kc][2] = sm[row_g * 36 + kc * 8 + t + 4];
        qa[kc][3] = sm[(row_g + 8) * 36 + kc * 8 + t + 4];
    }

    // ---- preload this thread's bias+mask values into regs (own stripe) ----
    float2 bia0[8], bia1[8];
#pragma unroll
    for (int nt = 0; nt < 8; nt++) {
        bia0[nt] = *(const float2*)(sm + ASM_B + row_g * 68 + nt * 8 + 2 * t);
        bia1[nt] = *(const float2*)(sm + ASM_B + (row_g + 8) * 68 + nt * 8 + 2 * t);
    }
    __syncwarp();   // all lanes' bias reads complete before P overwrites stripe

    // ---- scores + exp + P store (into own 16-row stripe of sBM) ----
    float rs0 = 0.f, rs1 = 0.f;
    float* sPw = sm + ASM_B + ws * 16 * 68;
#pragma unroll
    for (int nt = 0; nt < 8; nt++) {
        float acc[4] = {0.f, 0.f, 0.f, 0.f};
#pragma unroll
        for (int kc = 0; kc < 4; kc++) {
            float b2[2];
            b2[0] = sm[ASM_K + (nt * 8 + g) * 36 + kc * 8 + t];
            b2[1] = sm[ASM_K + (nt * 8 + g) * 36 + kc * 8 + t + 4];
            mma_tf32(acc, qa[kc], b2);
        }
        float p0 = f2tf32(__expf(acc[0] + bia0[nt].x));
        float p1 = f2tf32(__expf(acc[1] + bia0[nt].y));
        float p2 = f2tf32(__expf(acc[2] + bia1[nt].x));
        float p3 = f2tf32(__expf(acc[3] + bia1[nt].y));
        rs0 += p0 + p1;
        rs1 += p2 + p3;
        *(float2*)(sPw + g * 68 + nt * 8 + 2 * t) = make_float2(p0, p1);
        *(float2*)(sPw + (g + 8) * 68 + nt * 8 + 2 * t) = make_float2(p2, p3);
    }
    // row sums: reduce over t within each quad
    rs0 += __shfl_xor_sync(0xffffffffu, rs0, 1);
    rs0 += __shfl_xor_sync(0xffffffffu, rs0, 2);
    rs1 += __shfl_xor_sync(0xffffffffu, rs1, 1);
    rs1 += __shfl_xor_sync(0xffffffffu, rs1, 2);
    __syncwarp();

    // ---- PV: O(16x32) per warp ----
    float oacc[4][4];
#pragma unroll
    for (int nd = 0; nd < 4; nd++)
#pragma unroll
        for (int e = 0; e < 4; e++) oacc[nd][e] = 0.f;

#pragma unroll
    for (int kc = 0; kc < 8; kc++) {
        float a[4];
        a[0] = sPw[g * 68 + kc * 8 + t];
        a[1] = sPw[(g + 8) * 68 + kc * 8 + t];
        a[2] = sPw[g * 68 + kc * 8 + t + 4];
        a[3] = sPw[(g + 8) * 68 + kc * 8 + t + 4];
#pragma unroll
        for (int nd = 0; nd < 4; nd++) {
            float b2[2];
            b2[0] = sm[ASM_V + (kc * 8 + t) * 36 + nd * 8 + g];
            b2[1] = sm[ASM_V + (kc * 8 + t + 4) * 36 + nd * 8 + g];
            mma_tf32(oacc[nd], a, b2);
        }
    }

    // ---- normalize + write out (tf32-rounded for proj GEMM) ----
    const float inv0 = 1.f / rs0;
    const float inv1 = 1.f / rs1;
#pragma unroll
    for (int nd = 0; nd < 4; nd++) {
        int d = nd * 8 + 2 * t;
        if (d < HD) {
            float2 v0 = make_float2(f2tf32(oacc[nd][0] * inv0), f2tf32(oacc[nd][1] * inv0));
            float2 v1 = make_float2(f2tf32(oacc[nd][2] * inv1), f2tf32(oacc[nd][3] * inv1));
            *(float2*)(out + (size_t)(w * NTOK + row_g) * CDIM + h * HD + d) = v0;
            *(float2*)(out + (size_t)(w * NTOK + row_g + 8) * CDIM + h * HD + d) = v1;
        }
    }
}

// ===========================================================================
extern "C" void kernel_launch(void* const* d_in, const int* in_sizes, int n_in,
                              void* d_out, int out_size)
{
    const float* x      = (const float*)d_in[0];
    const float* mask   = (const float*)d_in[1];
    const float* qkv_w  = (const float*)d_in[2];
    const float* qkv_b  = (const float*)d_in[3];
    const float* proj_w = (const float*)d_in[4];
    const float* proj_b = (const float*)d_in[5];
    const float* rpb    = (const float*)d_in[6];
    float* out = (float*)d_out;

    void *p_qkv = nullptr, *p_att = nullptr, *p_wq = nullptr, *p_wp = nullptr;
    cudaGetSymbolAddress(&p_qkv, g_qkv);
    cudaGetSymbolAddress(&p_att, g_att);
    cudaGetSymbolAddress(&p_wq, g_wq);
    cudaGetSymbolAddress(&p_wp, g_wp);
    float* qkv = (float*)p_qkv;
    float* att = (float*)p_att;   // rounded x, then attention output
    float* wq  = (float*)p_wq;
    float* wp  = (float*)p_wp;

    const int M = NW * NTOK;                                  // 524288
    const int gemm_smem = 3 * GSTAGE_WORDS * sizeof(float);   // 110592
    const int attn_smem = ATT_SMEM_FLOATS * sizeof(float);    // 45056

    static bool attr_set = false;
    if (!attr_set) {
        cudaFuncSetAttribute(mma_gemm_tn,
                             cudaFuncAttributeMaxDynamicSharedMemorySize, gemm_smem);
        cudaFuncSetAttribute(attn_mma_kernel,
                             cudaFuncAttributeMaxDynamicSharedMemorySize, attn_smem);
        attr_set = true;
    }

    // 0) Pre-round inputs to tf32; expand RPB
    round_kernel<<<2048, 256>>>(x, att, M * CDIM / 4);          // x -> g_att
    round_kernel<<<64, 256>>>(qkv_w, wq, 3 * CDIM * CDIM / 4);
    round_kernel<<<32, 256>>>(proj_w, wp, CDIM * CDIM / 4);
    bias_expand_kernel<<<HEADS, 256>>>(rpb);

    // 1) QKV projection: [M,180] @ [540,180]^T + b -> [M,540]
    {
        dim3 grid((3 * CDIM + 127) / 128, M / 128);
        mma_gemm_tn<<<grid, 256, gemm_smem>>>(att, wq, qkv_b, qkv, 3 * CDIM);
    }

    // 2) MMA attention (1D grid, wi-major for mask L2 reuse); writes g_att
    attn_mma_kernel<<<NW * HEADS, 128, attn_smem>>>(qkv, mask, att);

    // 3) Output projection: [M,180] @ [180,180]^T + b -> [M,180]
    {
        dim3 grid((CDIM + 127) / 128, M / 128);
        mma_gemm_tn<<<grid, 256, gemm_smem>>>(att, wp, proj_b, out, CDIM);
    }
}